// round 1
// baseline (speedup 1.0000x reference)
#include <cuda_runtime.h>
#include <cstdint>
#include <cstddef>

// RWW whole-brain sim: 20000 sequential steps of
//   y = Con @ S_E ; per-region nonlinear Euler update ; write history.
// Strategy: single 8-CTA cluster (one launch, graph-capturable).
//   - Con_Mtx lives entirely in REGISTERS: 512 regions / 8 CTAs = 64 rows/CTA,
//     256 threads/CTA, each thread owns (1 row x 128 cols) = 128 fp32 regs.
//   - S_E vector double-buffered in SMEM, broadcast cluster-wide via
//     st.shared::cluster; one barrier.cluster per step.
//   - Bank-padded x layout (quarter stride 2576B = 16 mod 128) makes the
//     4 column-quarter lanes conflict-free with 8-way broadcast.

#define NREG    512
#define NSTEPS  20000
#define NCTAS   8
#define ROWSPC  64          // regions (rows) per CTA
#define NTHR    256         // 64 rows x 4 column-quarters

// x-vector smem layout (floats): quarter stride QF, parity stride PF.
// byte quarter stride = 2576 (== 16 mod 128 -> per-quarter bank offset)
#define QF 644
#define PF 2576
#define SMEM_BYTES (2 * PF * 4)   // 20608 B

__device__ __forceinline__ float Hfun(float I, float a, float b, float d, float bigc) {
    float x     = fmaf(a, I, -b);
    float numer = fabsf(x) + 1e-9f;
    float neg   = -d * x;
    float denom;
    if (neg > 50.0f) {
        denom = fabsf(1.0f - bigc * neg) + 1e-9f * d;
    } else {
        denom = fabsf(1.0f - expf(fminf(neg, 51.0f))) + 1e-9f * d;
    }
    return numer / denom;
}

extern __shared__ float smx[];

__global__ void __launch_bounds__(NTHR, 1) __cluster_dims__(NCTAS, 1, 1)
rww_kernel(const float* __restrict__ init_state,   // (512, 2)
           const float* __restrict__ Con,          // (512, 512) row-major
           const float* __restrict__ vofT,         // (20000, 512)
           float* __restrict__ out)                // 1024 final + 20000*1024 hist
{
    const int tid = (int)threadIdx.x;
    const int cta = (int)blockIdx.x;        // == cluster rank (grid = 1 cluster)
    const int r   = tid >> 2;               // local row 0..63
    const int q   = tid & 3;                // column quarter 0..3
    const bool lead = (q == 0);
    const int j   = cta * ROWSPC + r;       // global region index of this row

    // ---- Con row segment -> registers (128 fp32) ----
    float c[128];
    {
        const float4* src = (const float4*)(Con + (size_t)j * NREG + (size_t)q * 128);
        #pragma unroll
        for (int it = 0; it < 32; ++it) {
            float4 t4 = src[it];
            c[4*it+0] = t4.x; c[4*it+1] = t4.y;
            c[4*it+2] = t4.z; c[4*it+3] = t4.w;
        }
    }

    // ---- init x (parity 0) : padded layout x[j] @ (j>>7)*QF + (j&127) ----
    for (int k = tid; k < NREG; k += NTHR)
        smx[(k >> 7) * QF + (k & 127)] = init_state[2 * k];

    // ---- per-region state in registers of lead threads ----
    float sE = 0.0f, sI = 0.0f;
    if (lead) { sE = init_state[2 * j]; sI = init_state[2 * j + 1]; }

    // smem u32 address of region j's slot in the x buffer, both parities
    uint32_t slot0, slot1;
    {
        uint32_t sb;
        asm("{ .reg .u64 t; cvta.to.shared.u64 t, %1; cvt.u32.u64 %0, t; }"
            : "=r"(sb) : "l"(smx));
        uint32_t off = (uint32_t)((((cta >> 1) * QF) + ((cta & 1) * 64 + r)) * 4);
        slot0 = sb + off;                       // parity 0
        slot1 = sb + (uint32_t)(PF * 4) + off;  // parity 1
    }

    __syncthreads();   // x parity-0 ready (peers never read our smem directly)

    const float4* x4base0 = (const float4*)(smx)      + q * (QF / 4);
    const float4* x4base1 = (const float4*)(smx + PF) + q * (QF / 4);
    float2* outv = (float2*)out;

    for (int t = 0; t < NSTEPS; ++t) {
        const int p = t & 1;

        // prefetch noise sample early (consumed after matvec)
        float v = 0.0f;
        if (lead) v = __ldg(vofT + (size_t)t * NREG + j);

        // ---- matvec: this thread's 128 columns, C in regs, x from smem ----
        const float4* x4 = p ? x4base1 : x4base0;
        float a0 = 0.f, a1 = 0.f, a2 = 0.f, a3 = 0.f;
        #pragma unroll
        for (int it = 0; it < 32; ++it) {
            float4 xv = x4[it];
            a0 = fmaf(c[4*it+0], xv.x, a0);
            a1 = fmaf(c[4*it+1], xv.y, a1);
            a2 = fmaf(c[4*it+2], xv.z, a2);
            a3 = fmaf(c[4*it+3], xv.w, a3);
        }
        float acc = (a0 + a1) + (a2 + a3);
        acc += __shfl_xor_sync(0xffffffffu, acc, 1);
        acc += __shfl_xor_sync(0xffffffffu, acc, 2);
        // lanes with q==0 now hold the full row dot product

        if (lead) {
            // I_E = W_E*I_0 + W_PLUS*J_NMDA*S_E + G*J_NMDA*Net - J*S_I
            float I_E = 0.382f  + 0.21f  * sE + 3.0f * acc - sI;
            // I_I = W_I*I_0 + J_NMDA*S_E - S_I   (LAMBDA = 0)
            float I_I = 0.2674f + 0.15f  * sE - sI;
            float rE = Hfun(I_E, 310.0f, 125.0f, 0.16f,  1e9f);
            float rI = Hfun(I_I, 615.0f, 177.0f, 0.087f, 1e5f);
            float dE = -sE * 0.01f + (1.0f - sE) * 6.41e-4f * rE + 0.01f * v;
            float dI = -sI * 0.1f  + 1.0e-3f * rI + 0.01f * v;
            sE = fmaf(1e-4f, dE, sE);
            sI = fmaf(1e-4f, dI, sI);

            // history (post-update, matching reference scan output)
            outv[512 + (size_t)t * NREG + j] = make_float2(sE, sI);

            // broadcast new S_E into every CTA's x buffer, parity p^1
            uint32_t dst = p ? slot0 : slot1;
            #pragma unroll
            for (int d = 0; d < NCTAS; ++d) {
                uint32_t ra;
                asm("mapa.shared::cluster.u32 %0, %1, %2;"
                    : "=r"(ra) : "r"(dst), "r"(d));
                asm volatile("st.shared::cluster.f32 [%0], %1;"
                             :: "r"(ra), "f"(sE));
            }
        }

        // one cluster barrier per step: arrive(release) orders the DSMEM
        // stores; wait(acquire) makes them visible for the next matvec.
        asm volatile("barrier.cluster.arrive.aligned;" ::: "memory");
        asm volatile("barrier.cluster.wait.aligned;"   ::: "memory");
    }

    // final state_vals (first 512 float2 of d_out)
    if (lead) outv[j] = make_float2(sE, sI);
}

extern "C" void kernel_launch(void* const* d_in, const int* in_sizes, int n_in,
                              void* d_out, int out_size) {
    // identify inputs by element count (robust to ordering)
    const float* init = nullptr;
    const float* con  = nullptr;
    const float* v    = nullptr;
    for (int i = 0; i < n_in; ++i) {
        if      (in_sizes[i] == NREG * 2)      init = (const float*)d_in[i];
        else if (in_sizes[i] == NREG * NREG)   con  = (const float*)d_in[i];
        else if (in_sizes[i] == NSTEPS * NREG) v    = (const float*)d_in[i];
    }
    rww_kernel<<<NCTAS, NTHR, SMEM_BYTES>>>(init, con, v, (float*)d_out);
    (void)out_size;
}